// round 5
// baseline (speedup 1.0000x reference)
#include <cuda_runtime.h>
#include <math.h>

#define H 1024
#define V 50257
#define L 12
#define NB 148
#define NT 1024
#define NWARP (NB * 32)        // 4736

#define V4 12564               // full float4's in V (scalar tail = elem 50256)
#define SLICE_W 85             // 148*85 >= 12565

// ---------------- scratch ----------------
__device__ float g_attn_logit[L];
__device__ __align__(16) float g_hhp[4096];   // Whh@h0 partials (4/row)
__device__ __align__(16) float g_xp[4096];    // comb partials
__device__ __align__(16) float g_ihp[4096];   // Wih@x partials
__device__ __align__(16) float g_logits[V];
__device__ float g_sm[NB];
__device__ float g_ss[NB];

__device__ unsigned g_bar_arrive = 0;
__device__ volatile unsigned g_bar_gen = 0;

__device__ __forceinline__ void grid_barrier()
{
    __syncthreads();
    if (threadIdx.x == 0) {
        __threadfence();
        unsigned gen = g_bar_gen;
        unsigned t = atomicAdd(&g_bar_arrive, 1u);
        if (t == NB - 1) {
            g_bar_arrive = 0;
            __threadfence();
            g_bar_gen = gen + 1;
        } else {
            while (g_bar_gen == gen) { }
            __threadfence();
        }
    }
    __syncthreads();
}

__device__ __forceinline__ float warp_sum(float v)
{
    #pragma unroll
    for (int o = 16; o; o >>= 1) v += __shfl_xor_sync(0xffffffffu, v, o);
    return v;
}
__device__ __forceinline__ float warp_max(float v)
{
    #pragma unroll
    for (int o = 16; o; o >>= 1) v = fmaxf(v, __shfl_xor_sync(0xffffffffu, v, o));
    return v;
}
__device__ __forceinline__ void prefetch_row(const float* rowp, int lane)
{
    asm volatile("prefetch.global.L2 [%0];" :: "l"(rowp + lane * 32));
}

__global__ __launch_bounds__(NT, 1) void fused(
    const int*   __restrict__ tok,
    const float* __restrict__ hidden,
    const float* __restrict__ enc,
    const float* __restrict__ emb,
    const float* __restrict__ attn_W,
    const float* __restrict__ attn_b,
    const float* __restrict__ comb_W,
    const float* __restrict__ comb_b,
    const float* __restrict__ Wih,
    const float* __restrict__ Whh,
    const float* __restrict__ bih,
    const float* __restrict__ bhh,
    const float* __restrict__ out_W,
    const float* __restrict__ out_b,
    float* __restrict__ out_logp,
    float* __restrict__ out_h,
    float* __restrict__ out_attnw)
{
    const int tid  = threadIdx.x;
    const int bid  = blockIdx.x;
    const int lane = tid & 31;
    const int wid  = tid >> 5;
    const int gw   = bid * 32 + wid;

    __shared__ float red[32];
    __shared__ float red2[32];
    __shared__ float s_logit[32][12];
    __shared__ __align__(16) float sA[H];
    __shared__ __align__(16) float sB[H];
    __shared__ float sh_c;

    const int token = tok[0];
    const float* __restrict__ erow = emb + (size_t)token * H;

    // ======== P1: attn logits (0..11) | Whh partials (12..139) | prefetch band0 ====
    if (bid < L) {
        float p = erow[tid] * attn_W[bid * (2 * H) + tid]
                + hidden[tid] * attn_W[bid * (2 * H) + H + tid];
        p = warp_sum(p);
        if (lane == 0) red[wid] = p;
        __syncthreads();
        if (wid == 0) {
            float v = warp_sum(red[lane]);
            if (lane == 0) g_attn_logit[bid] = v + attn_b[bid];
        }
    } else if (bid < 140) {
        sA[tid] = hidden[tid];
        __syncthreads();
        const int lw  = gw - L * 32;
        const int row = lw >> 2, q = lw & 3;
        const float4* __restrict__ wr = (const float4*)Whh + (size_t)row * 256 + q * 64;
        const float4* vh = (const float4*)sA + q * 64;
        float s = 0.f;
        #pragma unroll
        for (int k = 0; k < 2; k++) {
            float4 wv = wr[k * 32 + lane];
            float4 xv = vh[k * 32 + lane];
            s = fmaf(wv.x, xv.x, fmaf(wv.y, xv.y, fmaf(wv.z, xv.z, fmaf(wv.w, xv.w, s))));
        }
        s = warp_sum(s);
        if (lane == 0) g_hhp[lw] = s;
    } else {
        // prefetch band 0: rows [0, 4736) over 256 warps
        const int iw = (bid - 140) * 32 + wid;
        for (int r = iw; r < NWARP; r += 256)
            prefetch_row(out_W + (size_t)r * H, lane);
    }
    grid_barrier();

    // ======== P2: comb partials (0..127) | prefetch bands 1-2 (128..147) ==========
    if (bid < 128) {
        float aw[L];
        float mm = -INFINITY;
        #pragma unroll
        for (int j = 0; j < L; j++) { aw[j] = g_attn_logit[j]; mm = fmaxf(mm, aw[j]); }
        float sum = 0.f;
        #pragma unroll
        for (int j = 0; j < L; j++) { aw[j] = expf(aw[j] - mm); sum += aw[j]; }
        float inv = 1.f / sum;
        #pragma unroll
        for (int j = 0; j < L; j++) aw[j] *= inv;
        if (bid == 0 && tid < L) out_attnw[tid] = aw[tid];

        sA[tid] = erow[tid];
        float a = 0.f;
        #pragma unroll
        for (int j = 0; j < L; j++) a = fmaf(aw[j], enc[j * H + tid], a);
        sB[tid] = a;
        __syncthreads();

        const int row = gw >> 2, q = gw & 3;
        const float4* __restrict__ wr = (const float4*)comb_W + (size_t)row * 512 + q * 128;
        const float4* vv = ((q < 2) ? (const float4*)sA : (const float4*)sB) + (q & 1) * 128;
        float s = 0.f;
        #pragma unroll
        for (int k = 0; k < 4; k++) {
            float4 wv = wr[k * 32 + lane];
            float4 xv = vv[k * 32 + lane];
            s = fmaf(wv.x, xv.x, fmaf(wv.y, xv.y, fmaf(wv.z, xv.z, fmaf(wv.w, xv.w, s))));
        }
        s = warp_sum(s);
        if (lane == 0) g_xp[gw] = s;
    } else {
        // prefetch bands 1-2: rows [4736, 14208) over 640 warps
        const int iw = (bid - 128) * 32 + wid;
        for (int r = NWARP + iw; r < 3 * NWARP; r += 640)
            prefetch_row(out_W + (size_t)r * H, lane);
    }
    grid_barrier();

    // ======== P3: Wih partials (0..127) | prefetch bands 3-4 (128..147) ===========
    if (bid < 128) {
        float4 xp = ((const float4*)g_xp)[tid];
        sA[tid] = fmaxf(xp.x + xp.y + xp.z + xp.w + comb_b[tid], 0.f);
        __syncthreads();

        const int row = gw >> 2, q = gw & 3;
        const float4* __restrict__ wr = (const float4*)Wih + (size_t)row * 256 + q * 64;
        const float4* vx = (const float4*)sA + q * 64;
        float s = 0.f;
        #pragma unroll
        for (int k = 0; k < 2; k++) {
            float4 wv = wr[k * 32 + lane];
            float4 xv = vx[k * 32 + lane];
            s = fmaf(wv.x, xv.x, fmaf(wv.y, xv.y, fmaf(wv.z, xv.z, fmaf(wv.w, xv.w, s))));
        }
        s = warp_sum(s);
        if (lane == 0) g_ihp[gw] = s;
    } else {
        // prefetch bands 3-4: rows [14208, 23680) over 640 warps
        const int iw = (bid - 128) * 32 + wid;
        for (int r = 3 * NWARP + iw; r < 5 * NWARP && r < V; r += 640)
            prefetch_row(out_W + (size_t)r * H, lane);
    }
    grid_barrier();

    // ======== P4: h combine + logits GEMV + per-block (m,s) ======================
    {
        float4 ih = ((const float4*)g_ihp)[tid];
        float4 hh = ((const float4*)g_hhp)[tid];
        float h = tanhf(ih.x + ih.y + ih.z + ih.w +
                        hh.x + hh.y + hh.z + hh.w + bih[tid] + bhh[tid]);
        sA[tid] = h;
        if (bid == 0) out_h[tid] = h;
    }
    __syncthreads();
    {
        const float4* h4 = (const float4*)sA;
        float4 hr[8];
        #pragma unroll
        for (int k = 0; k < 8; k++) hr[k] = h4[k * 32 + lane];

        int t = 0;
        int row = gw;
        for (; row + NWARP < V; row += 2 * NWARP) {
            const float4* __restrict__ w0 = (const float4*)out_W + (size_t)row * 256 + lane;
            const float4* __restrict__ w1 = (const float4*)out_W + (size_t)(row + NWARP) * 256 + lane;
            float a0 = 0.f, a1 = 0.f;
            #pragma unroll
            for (int k = 0; k < 8; k++) {
                float4 v0 = w0[k * 32];
                float4 v1 = w1[k * 32];
                a0 = fmaf(v0.x, hr[k].x, fmaf(v0.y, hr[k].y, fmaf(v0.z, hr[k].z, fmaf(v0.w, hr[k].w, a0))));
                a1 = fmaf(v1.x, hr[k].x, fmaf(v1.y, hr[k].y, fmaf(v1.z, hr[k].z, fmaf(v1.w, hr[k].w, a1))));
            }
            #pragma unroll
            for (int o = 16; o; o >>= 1) {
                a0 += __shfl_xor_sync(0xffffffffu, a0, o);
                a1 += __shfl_xor_sync(0xffffffffu, a1, o);
            }
            float l0 = a0 + out_b[row];
            float l1 = a1 + out_b[row + NWARP];
            if (lane == 0) {
                g_logits[row]         = l0;
                g_logits[row + NWARP] = l1;
                s_logit[wid][t]       = l0;
                s_logit[wid][t + 1]   = l1;
            }
            t += 2;
        }
        if (row < V) {
            const float4* __restrict__ w0 = (const float4*)out_W + (size_t)row * 256 + lane;
            float a0 = 0.f;
            #pragma unroll
            for (int k = 0; k < 8; k++) {
                float4 v0 = w0[k * 32];
                a0 = fmaf(v0.x, hr[k].x, fmaf(v0.y, hr[k].y, fmaf(v0.z, hr[k].z, fmaf(v0.w, hr[k].w, a0))));
            }
            a0 = warp_sum(a0);
            float l0 = a0 + out_b[row];
            if (lane == 0) { g_logits[row] = l0; s_logit[wid][t] = l0; }
            t += 1;
        }
        __syncwarp();
        // warp-local LSE over this warp's t logits (t uniform across lanes)
        float v = (lane < t) ? s_logit[wid][lane] : -INFINITY;
        float wm = warp_max(v);
        float e  = (lane < t) ? expf(v - wm) : 0.f;
        float ws = warp_sum(e);
        if (lane == 0) { red[wid] = wm; red2[wid] = ws; }
        __syncthreads();
        if (wid == 0) {
            float bm = red[lane], bs = red2[lane];
            #pragma unroll
            for (int o = 16; o; o >>= 1) {
                float om = __shfl_xor_sync(0xffffffffu, bm, o);
                float os = __shfl_xor_sync(0xffffffffu, bs, o);
                float nm = fmaxf(bm, om);
                bs = bs * expf(bm - nm) + os * expf(om - nm);
                bm = nm;
            }
            if (lane == 0) { g_sm[bid] = bm; g_ss[bid] = bs; }
        }
    }
    grid_barrier();

    // ======== P5: redundant merge of 148 (m,s) + write logp =======================
    if (wid == 0) {
        float bm = -INFINITY, bs = 0.f;
        for (int i = lane; i < NB; i += 32) {
            float pm = g_sm[i], ps = g_ss[i];
            float nm = fmaxf(bm, pm);
            bs = bs * expf(bm - nm) + ps * expf(pm - nm);
            bm = nm;
        }
        #pragma unroll
        for (int o = 16; o; o >>= 1) {
            float om = __shfl_xor_sync(0xffffffffu, bm, o);
            float os = __shfl_xor_sync(0xffffffffu, bs, o);
            float nm = fmaxf(bm, om);
            bs = bs * expf(bm - nm) + os * expf(om - nm);
            bm = nm;
        }
        if (lane == 0) sh_c = bm + logf(bs);
    }
    __syncthreads();
    const float c = sh_c;
    if (tid < SLICE_W) {
        int i4 = bid * SLICE_W + tid;
        if (i4 < V4) {
            float4 v = ((const float4*)g_logits)[i4];
            v.x -= c; v.y -= c; v.z -= c; v.w -= c;
            ((float4*)out_logp)[i4] = v;
        } else if (i4 == V4) {
            out_logp[V - 1] = g_logits[V - 1] - c;
        }
    }
}

// ---------------- launcher ----------------------------------------------------
extern "C" void kernel_launch(void* const* d_in, const int* in_sizes, int n_in,
                              void* d_out, int out_size)
{
    const int*   tok    = (const int*)  d_in[0];
    const float* hidden = (const float*)d_in[1];
    const float* enc    = (const float*)d_in[2];
    const float* emb    = (const float*)d_in[3];
    const float* attn_W = (const float*)d_in[4];
    const float* attn_b = (const float*)d_in[5];
    const float* comb_W = (const float*)d_in[6];
    const float* comb_b = (const float*)d_in[7];
    const float* Wih    = (const float*)d_in[8];
    const float* Whh    = (const float*)d_in[9];
    const float* bih    = (const float*)d_in[10];
    const float* bhh    = (const float*)d_in[11];
    const float* out_W  = (const float*)d_in[12];
    const float* out_b  = (const float*)d_in[13];

    float* out = (float*)d_out;
    fused<<<NB, NT>>>(tok, hidden, enc, emb, attn_W, attn_b,
                      comb_W, comb_b, Wih, Whh, bih, bhh, out_W, out_b,
                      out, out + V, out + V + H);
}

// round 6
// speedup vs baseline: 1.8572x; 1.8572x over previous
#include <cuda_runtime.h>
#include <math.h>

#define H 1024
#define V 50257
#define L 12
#define NB 148
#define NT 1024
#define NWARP (NB * 32)        // 4736

#define V4 12564               // full float4's in V (scalar tail = elem 50256)
#define SLICE_W 85             // 148*85 >= 12565

// ---------------- scratch ----------------
__device__ __align__(16) float g_hhp[2048];   // Whh@h0 partials (2/row)
__device__ __align__(16) float g_xp[2048];    // comb partials (2/row)
__device__ __align__(16) float g_ihp[2048];   // Wih@x partials (2/row)
__device__ __align__(16) float g_logits[V];
__device__ float g_sm[NB];
__device__ float g_ss[NB];

__device__ unsigned g_bar_arrive = 0;
__device__ volatile unsigned g_bar_gen = 0;

__device__ __forceinline__ void grid_barrier()
{
    __syncthreads();
    if (threadIdx.x == 0) {
        __threadfence();
        unsigned gen = g_bar_gen;
        unsigned t = atomicAdd(&g_bar_arrive, 1u);
        if (t == NB - 1) {
            g_bar_arrive = 0;
            __threadfence();
            g_bar_gen = gen + 1;
        } else {
            while (g_bar_gen == gen) { }
            __threadfence();
        }
    }
    __syncthreads();
}

__device__ __forceinline__ float warp_sum(float v)
{
    #pragma unroll
    for (int o = 16; o; o >>= 1) v += __shfl_xor_sync(0xffffffffu, v, o);
    return v;
}
__device__ __forceinline__ float warp_max(float v)
{
    #pragma unroll
    for (int o = 16; o; o >>= 1) v = fmaxf(v, __shfl_xor_sync(0xffffffffu, v, o));
    return v;
}
__device__ __forceinline__ void prefetch_row(const float* rowp, int lane)
{
    asm volatile("prefetch.global.L2 [%0];" :: "l"(rowp + lane * 32));
}

__global__ __launch_bounds__(NT, 1) void fused(
    const int*   __restrict__ tok,
    const float* __restrict__ hidden,
    const float* __restrict__ enc,
    const float* __restrict__ emb,
    const float* __restrict__ attn_W,
    const float* __restrict__ attn_b,
    const float* __restrict__ comb_W,
    const float* __restrict__ comb_b,
    const float* __restrict__ Wih,
    const float* __restrict__ Whh,
    const float* __restrict__ bih,
    const float* __restrict__ bhh,
    const float* __restrict__ out_W,
    const float* __restrict__ out_b,
    float* __restrict__ out_logp,
    float* __restrict__ out_h,
    float* __restrict__ out_attnw)
{
    const int tid  = threadIdx.x;
    const int bid  = blockIdx.x;
    const int lane = tid & 31;
    const int wid  = tid >> 5;
    const int gw   = bid * 32 + wid;

    __shared__ float red[32];
    __shared__ float red2[32];
    __shared__ float s_alog[L];
    __shared__ float s_logit[32][12];
    __shared__ __align__(16) float sE[H];     // embedded -> x -> h_new (reused)
    __shared__ __align__(16) float sHid[H];   // hidden
    __shared__ __align__(16) float sAtt[H];   // attn_applied
    __shared__ float sh_c;

    const int token = tok[0];
    const float* __restrict__ erow = emb + (size_t)token * H;

    // ================= P1: attention (redundant) + comb/Whh partials ==============
    sE[tid]   = erow[tid];
    sHid[tid] = hidden[tid];
    __syncthreads();

    if (wid < L) {
        // attention logit row `wid` : dot over [embedded ; hidden] (2H)
        const float4* __restrict__ wr = (const float4*)attn_W + wid * 512;
        const float4* e4 = (const float4*)sE;
        const float4* h4 = (const float4*)sHid;
        float s = 0.f;
        #pragma unroll
        for (int k = 0; k < 8; k++) {
            float4 wv = wr[k * 32 + lane];
            float4 xv = e4[k * 32 + lane];
            s = fmaf(wv.x, xv.x, fmaf(wv.y, xv.y, fmaf(wv.z, xv.z, fmaf(wv.w, xv.w, s))));
        }
        #pragma unroll
        for (int k = 0; k < 8; k++) {
            float4 wv = wr[256 + k * 32 + lane];
            float4 xv = h4[k * 32 + lane];
            s = fmaf(wv.x, xv.x, fmaf(wv.y, xv.y, fmaf(wv.z, xv.z, fmaf(wv.w, xv.w, s))));
        }
        s = warp_sum(s);
        if (lane == 0) s_alog[wid] = s + attn_b[wid];
    }
    __syncthreads();

    // redundant 12-way softmax per thread
    float aw[L];
    {
        float mm = -INFINITY;
        #pragma unroll
        for (int j = 0; j < L; j++) { aw[j] = s_alog[j]; mm = fmaxf(mm, aw[j]); }
        float sum = 0.f;
        #pragma unroll
        for (int j = 0; j < L; j++) { aw[j] = expf(aw[j] - mm); sum += aw[j]; }
        float inv = 1.f / sum;
        #pragma unroll
        for (int j = 0; j < L; j++) aw[j] *= inv;
    }
    if (bid == 0 && tid < L) out_attnw[tid] = aw[tid];

    {
        float a = 0.f;
        #pragma unroll
        for (int j = 0; j < L; j++) a = fmaf(aw[j], enc[j * H + tid], a);
        sAtt[tid] = a;
    }
    __syncthreads();

    if (bid < 64) {
        // comb partials: row = gw>>1, half q = gw&1 (1024-elem segment)
        const int row = gw >> 1, q = gw & 1;
        const float4* __restrict__ wr = (const float4*)comb_W + (size_t)row * 512 + q * 256;
        const float4* vv = q ? (const float4*)sAtt : (const float4*)sE;
        float s = 0.f;
        #pragma unroll
        for (int k = 0; k < 8; k++) {
            float4 wv = wr[k * 32 + lane];
            float4 xv = vv[k * 32 + lane];
            s = fmaf(wv.x, xv.x, fmaf(wv.y, xv.y, fmaf(wv.z, xv.z, fmaf(wv.w, xv.w, s))));
        }
        s = warp_sum(s);
        if (lane == 0) g_xp[gw] = s;
    } else if (bid < 128) {
        // Whh partials: lw = gw-2048, row = lw>>1, 512-elem segment q
        const int lw = gw - 2048, row = lw >> 1, q = lw & 1;
        const float4* __restrict__ wr = (const float4*)Whh + (size_t)row * 256 + q * 128;
        const float4* vh = (const float4*)sHid + q * 128;
        float s = 0.f;
        #pragma unroll
        for (int k = 0; k < 4; k++) {
            float4 wv = wr[k * 32 + lane];
            float4 xv = vh[k * 32 + lane];
            s = fmaf(wv.x, xv.x, fmaf(wv.y, xv.y, fmaf(wv.z, xv.z, fmaf(wv.w, xv.w, s))));
        }
        s = warp_sum(s);
        if (lane == 0) g_hhp[lw] = s;
    } else {
        prefetch_row(out_W + (size_t)gw * H, lane);   // own first D1 row
    }
    grid_barrier();

    // ================= P2: x combine + Wih partials (blocks 0..63) ================
    if (bid < 64) {
        float2 xp = ((const float2*)g_xp)[tid];
        sE[tid] = fmaxf(xp.x + xp.y + comb_b[tid], 0.f);
        __syncthreads();

        const int row = gw >> 1, q = gw & 1;
        const float4* __restrict__ wr = (const float4*)Wih + (size_t)row * 256 + q * 128;
        const float4* vx = (const float4*)sE + q * 128;
        float s = 0.f;
        #pragma unroll
        for (int k = 0; k < 4; k++) {
            float4 wv = wr[k * 32 + lane];
            float4 xv = vx[k * 32 + lane];
            s = fmaf(wv.x, xv.x, fmaf(wv.y, xv.y, fmaf(wv.z, xv.z, fmaf(wv.w, xv.w, s))));
        }
        s = warp_sum(s);
        if (lane == 0) g_ihp[gw] = s;
    } else if (bid < 128) {
        prefetch_row(out_W + (size_t)gw * H, lane);             // own first row
    } else {
        prefetch_row(out_W + (size_t)(gw + NWARP) * H, lane);   // own second row
    }
    grid_barrier();

    // ================= P3: h combine (redundant) + logits GEMV + LSE ==============
    {
        float2 ih = ((const float2*)g_ihp)[tid];
        float2 hh = ((const float2*)g_hhp)[tid];
        float h = tanhf(ih.x + ih.y + hh.x + hh.y + bih[tid] + bhh[tid]);
        sE[tid] = h;
        if (bid == 0) out_h[tid] = h;
    }
    __syncthreads();
    {
        const float4* h4 = (const float4*)sE;
        float4 hr[8];
        #pragma unroll
        for (int k = 0; k < 8; k++) hr[k] = h4[k * 32 + lane];

        int t = 0;
        int row = gw;
        for (; row + NWARP < V; row += 2 * NWARP) {
            const float4* __restrict__ w0 = (const float4*)out_W + (size_t)row * 256 + lane;
            const float4* __restrict__ w1 = (const float4*)out_W + (size_t)(row + NWARP) * 256 + lane;
            float a0 = 0.f, a1 = 0.f;
            #pragma unroll
            for (int k = 0; k < 8; k++) {
                float4 v0 = w0[k * 32];
                float4 v1 = w1[k * 32];
                a0 = fmaf(v0.x, hr[k].x, fmaf(v0.y, hr[k].y, fmaf(v0.z, hr[k].z, fmaf(v0.w, hr[k].w, a0))));
                a1 = fmaf(v1.x, hr[k].x, fmaf(v1.y, hr[k].y, fmaf(v1.z, hr[k].z, fmaf(v1.w, hr[k].w, a1))));
            }
            #pragma unroll
            for (int o = 16; o; o >>= 1) {
                a0 += __shfl_xor_sync(0xffffffffu, a0, o);
                a1 += __shfl_xor_sync(0xffffffffu, a1, o);
            }
            float l0 = a0 + out_b[row];
            float l1 = a1 + out_b[row + NWARP];
            if (lane == 0) {
                g_logits[row]         = l0;
                g_logits[row + NWARP] = l1;
                s_logit[wid][t]       = l0;
                s_logit[wid][t + 1]   = l1;
            }
            t += 2;
        }
        if (row < V) {
            const float4* __restrict__ w0 = (const float4*)out_W + (size_t)row * 256 + lane;
            float a0 = 0.f;
            #pragma unroll
            for (int k = 0; k < 8; k++) {
                float4 v0 = w0[k * 32];
                a0 = fmaf(v0.x, hr[k].x, fmaf(v0.y, hr[k].y, fmaf(v0.z, hr[k].z, fmaf(v0.w, hr[k].w, a0))));
            }
            a0 = warp_sum(a0);
            float l0 = a0 + out_b[row];
            if (lane == 0) { g_logits[row] = l0; s_logit[wid][t] = l0; }
            t += 1;
        }
        __syncwarp();
        // warp-local LSE over this warp's t logits
        float v = (lane < t) ? s_logit[wid][lane] : -INFINITY;
        float wm = warp_max(v);
        float e  = (lane < t) ? expf(v - wm) : 0.f;
        float ws = warp_sum(e);
        if (lane == 0) { red[wid] = wm; red2[wid] = ws; }
        __syncthreads();
        if (wid == 0) {
            float bm = red[lane], bs = red2[lane];
            #pragma unroll
            for (int o = 16; o; o >>= 1) {
                float om = __shfl_xor_sync(0xffffffffu, bm, o);
                float os = __shfl_xor_sync(0xffffffffu, bs, o);
                float nm = fmaxf(bm, om);
                bs = bs * expf(bm - nm) + os * expf(om - nm);
                bm = nm;
            }
            if (lane == 0) { g_sm[bid] = bm; g_ss[bid] = bs; }
        }
    }
    grid_barrier();

    // ================= P4: redundant merge of 148 (m,s) + write logp ==============
    if (wid == 0) {
        float bm = -INFINITY, bs = 0.f;
        for (int i = lane; i < NB; i += 32) {
            float pm = g_sm[i], ps = g_ss[i];
            float nm = fmaxf(bm, pm);
            bs = bs * expf(bm - nm) + ps * expf(pm - nm);
            bm = nm;
        }
        #pragma unroll
        for (int o = 16; o; o >>= 1) {
            float om = __shfl_xor_sync(0xffffffffu, bm, o);
            float os = __shfl_xor_sync(0xffffffffu, bs, o);
            float nm = fmaxf(bm, om);
            bs = bs * expf(bm - nm) + os * expf(om - nm);
            bm = nm;
        }
        if (lane == 0) sh_c = bm + logf(bs);
    }
    __syncthreads();
    const float c = sh_c;
    if (tid < SLICE_W) {
        int i4 = bid * SLICE_W + tid;
        if (i4 < V4) {
            float4 v = ((const float4*)g_logits)[i4];
            v.x -= c; v.y -= c; v.z -= c; v.w -= c;
            ((float4*)out_logp)[i4] = v;
        } else if (i4 == V4) {
            out_logp[V - 1] = g_logits[V - 1] - c;
        }
    }
}

// ---------------- launcher ----------------------------------------------------
extern "C" void kernel_launch(void* const* d_in, const int* in_sizes, int n_in,
                              void* d_out, int out_size)
{
    const int*   tok    = (const int*)  d_in[0];
    const float* hidden = (const float*)d_in[1];
    const float* enc    = (const float*)d_in[2];
    const float* emb    = (const float*)d_in[3];
    const float* attn_W = (const float*)d_in[4];
    const float* attn_b = (const float*)d_in[5];
    const float* comb_W = (const float*)d_in[6];
    const float* comb_b = (const float*)d_in[7];
    const float* Wih    = (const float*)d_in[8];
    const float* Whh    = (const float*)d_in[9];
    const float* bih    = (const float*)d_in[10];
    const float* bhh    = (const float*)d_in[11];
    const float* out_W  = (const float*)d_in[12];
    const float* out_b  = (const float*)d_in[13];

    float* out = (float*)d_out;
    fused<<<NB, NT>>>(tok, hidden, enc, emb, attn_W, attn_b,
                      comb_W, comb_b, Wih, Whh, bih, bhh, out_W, out_b,
                      out, out + V, out + V + H);
}